// round 5
// baseline (speedup 1.0000x reference)
#include <cuda_runtime.h>

// Problem constants
#define CB 2
#define CS 2048
#define CD 1024
#define CH 16
#define CDK 64
#define CM (CB*CS)            // 4096 rows in the projection GEMMs

static const size_t HEAD_ELEMS = (size_t)CB*CH*CS*CDK;   // 4 Mi
static const size_t OUT_ELEMS  = (size_t)CB*CS*CD;       // 4,194,304
static const size_t ATTN_ELEMS = (size_t)CB*CH*CS*CS;    // 134,217,728

// Scratch (device globals: allocation-free rule)
__device__ float g_Q[(size_t)CB*CH*CS*CDK];
__device__ float g_K[(size_t)CB*CH*CS*CDK];
__device__ float g_V[(size_t)CB*CH*CS*CDK];
__device__ float g_ctx[(size_t)CB*CS*CD];
__device__ float g_attn[(size_t)CB*CH*CS*CS];   // fallback if d_out doesn't hold attn

// ---------------------------------------------------------------------------
// Kernel 1: fused Q/K/V projections.  C[m,n] = sum_k X[m,k] * W[n,k]
// M=4096, N=1024, K=1024.  Stores into [b,h,s,dk] layout.
// 128x128 tile, BK=8, 256 threads, 8x8 per-thread microtile.
// ---------------------------------------------------------------------------
__global__ __launch_bounds__(256) void proj_kernel(
    const float* __restrict__ Xq, const float* __restrict__ Xk, const float* __restrict__ Xv,
    const float* __restrict__ Wq, const float* __restrict__ Wk, const float* __restrict__ Wv)
{
    const int z = blockIdx.z;
    const float* A = (z == 0) ? Xq : (z == 1) ? Xk : Xv;
    const float* W = (z == 0) ? Wq : (z == 1) ? Wk : Wv;
    float* Out     = (z == 0) ? g_Q : (z == 1) ? g_K : g_V;

    const int K = CD;
    __shared__ float As[8][128];
    __shared__ float Bs[8][128];

    const int tid  = threadIdx.x;
    const int row0 = blockIdx.y * 128;
    const int col0 = blockIdx.x * 128;
    const int lr = tid >> 1;          // 0..127
    const int lc = (tid & 1) * 4;     // 0 or 4
    const int tx = tid & 15, ty = tid >> 4;

    float acc[8][8];
    #pragma unroll
    for (int i = 0; i < 8; i++)
        #pragma unroll
        for (int j = 0; j < 8; j++) acc[i][j] = 0.f;

    for (int k0 = 0; k0 < K; k0 += 8) {
        float4 av = *(const float4*)(A + (size_t)(row0 + lr) * K + k0 + lc);
        float4 wv = *(const float4*)(W + (size_t)(col0 + lr) * K + k0 + lc);
        As[lc+0][lr] = av.x; As[lc+1][lr] = av.y; As[lc+2][lr] = av.z; As[lc+3][lr] = av.w;
        Bs[lc+0][lr] = wv.x; Bs[lc+1][lr] = wv.y; Bs[lc+2][lr] = wv.z; Bs[lc+3][lr] = wv.w;
        __syncthreads();
        #pragma unroll
        for (int kk = 0; kk < 8; kk++) {
            float ra[8], rb[8];
            #pragma unroll
            for (int i = 0; i < 8; i++) ra[i] = As[kk][ty*8 + i];
            #pragma unroll
            for (int j = 0; j < 8; j++) rb[j] = Bs[kk][tx*8 + j];
            #pragma unroll
            for (int i = 0; i < 8; i++)
                #pragma unroll
                for (int j = 0; j < 8; j++) acc[i][j] += ra[i] * rb[j];
        }
        __syncthreads();
    }

    #pragma unroll
    for (int i = 0; i < 8; i++) {
        int m = row0 + ty*8 + i;
        int b = m >> 11;                // /S
        int s = m & (CS - 1);
        #pragma unroll
        for (int j = 0; j < 8; j++) {
            int n  = col0 + tx*8 + j;
            int h  = n >> 6;            // /DK
            int dk = n & (CDK - 1);
            Out[(((size_t)(b*CH + h))*CS + s)*CDK + dk] = acc[i][j];
        }
    }
}

// ---------------------------------------------------------------------------
// Kernel 2: scores = scale * Q @ K^T (causal).  Per (b,h): M=N=2048, K=64.
// 128x128 tile, fully-masked tiles skipped.  Writes only k<=q entries.
// ---------------------------------------------------------------------------
__global__ __launch_bounds__(256) void scores_kernel(float* __restrict__ attn_out, int use_internal)
{
    if (blockIdx.x > blockIdx.y) return;   // tile fully above diagonal
    float* attn = use_internal ? g_attn : attn_out;

    const int z = blockIdx.z;              // b*H + h
    const float* Qh = g_Q + (size_t)z * CS * CDK;
    const float* Kh = g_K + (size_t)z * CS * CDK;

    __shared__ float As[8][128];
    __shared__ float Bs[8][128];

    const int tid  = threadIdx.x;
    const int row0 = blockIdx.y * 128;     // q tile
    const int col0 = blockIdx.x * 128;     // k tile
    const int lr = tid >> 1;
    const int lc = (tid & 1) * 4;
    const int tx = tid & 15, ty = tid >> 4;

    float acc[8][8];
    #pragma unroll
    for (int i = 0; i < 8; i++)
        #pragma unroll
        for (int j = 0; j < 8; j++) acc[i][j] = 0.f;

    for (int k0 = 0; k0 < CDK; k0 += 8) {
        float4 av = *(const float4*)(Qh + (size_t)(row0 + lr) * CDK + k0 + lc);
        float4 wv = *(const float4*)(Kh + (size_t)(col0 + lr) * CDK + k0 + lc);
        As[lc+0][lr] = av.x; As[lc+1][lr] = av.y; As[lc+2][lr] = av.z; As[lc+3][lr] = av.w;
        Bs[lc+0][lr] = wv.x; Bs[lc+1][lr] = wv.y; Bs[lc+2][lr] = wv.z; Bs[lc+3][lr] = wv.w;
        __syncthreads();
        #pragma unroll
        for (int kk = 0; kk < 8; kk++) {
            float ra[8], rb[8];
            #pragma unroll
            for (int i = 0; i < 8; i++) ra[i] = As[kk][ty*8 + i];
            #pragma unroll
            for (int j = 0; j < 8; j++) rb[j] = Bs[kk][tx*8 + j];
            #pragma unroll
            for (int i = 0; i < 8; i++)
                #pragma unroll
                for (int j = 0; j < 8; j++) acc[i][j] += ra[i] * rb[j];
        }
        __syncthreads();
    }

    const float scale = 0.125f;   // 1/sqrt(DK)
    #pragma unroll
    for (int i = 0; i < 8; i++) {
        int q = row0 + ty*8 + i;
        #pragma unroll
        for (int j = 0; j < 8; j++) {
            int k = col0 + tx*8 + j;
            if (k <= q)
                attn[((size_t)z * CS + q) * CS + k] = acc[i][j] * scale;
        }
    }
}

// ---------------------------------------------------------------------------
// Kernel 3: row softmax.  One block per (b,h,q) row; smem-resident row.
// Writes normalized weights for k<=q, exact zeros for k>q (matches exp(-1e9)).
// ---------------------------------------------------------------------------
__global__ __launch_bounds__(256) void softmax_kernel(float* __restrict__ attn_out, int use_internal)
{
    float* attn = use_internal ? g_attn : attn_out;
    __shared__ float row[CS];
    __shared__ float red[8];

    const int r   = blockIdx.x;            // 0 .. B*H*S-1
    const int q   = r & (CS - 1);
    const size_t base = (size_t)r * CS;
    const int len = q + 1;
    const int tid = threadIdx.x;

    float m = -1e30f;
    for (int i = tid; i < len; i += 256) {
        float v = attn[base + i];
        row[i] = v;
        m = fmaxf(m, v);
    }
    #pragma unroll
    for (int o = 16; o; o >>= 1) m = fmaxf(m, __shfl_xor_sync(0xffffffffu, m, o));
    if ((tid & 31) == 0) red[tid >> 5] = m;
    __syncthreads();
    m = red[0];
    #pragma unroll
    for (int i = 1; i < 8; i++) m = fmaxf(m, red[i]);
    __syncthreads();

    float s = 0.f;
    for (int i = tid; i < len; i += 256) {
        float e = __expf(row[i] - m);
        row[i] = e;
        s += e;
    }
    #pragma unroll
    for (int o = 16; o; o >>= 1) s += __shfl_xor_sync(0xffffffffu, s, o);
    if ((tid & 31) == 0) red[tid >> 5] = s;
    __syncthreads();
    s = red[0];
    #pragma unroll
    for (int i = 1; i < 8; i++) s += red[i];

    const float inv = 1.f / s;
    for (int i = tid; i < len; i += 256) attn[base + i] = row[i] * inv;
    for (int i = len + tid; i < CS; i += 256) attn[base + i] = 0.f;
}

// ---------------------------------------------------------------------------
// Kernel 4: context = attn @ V.  Per (b,h): M=2048, N=64, K up to q-tile end.
// 128x64 tile, BK=16, 256 threads, 8x4 microtile.  Stores [b,s,h,dk]=[b,s,d].
// ---------------------------------------------------------------------------
__global__ __launch_bounds__(256) void context_kernel(const float* __restrict__ attn_in, int use_internal)
{
    const float* attn = use_internal ? g_attn : attn_in;
    const int z  = blockIdx.y;             // b*H + h
    const int qt = blockIdx.x;             // q tile (0..15)
    const float* Ah = attn + (size_t)z * CS * CS;
    const float* Vh = g_V  + (size_t)z * CS * CDK;

    __shared__ float As[16][128];
    __shared__ float Vs[16][64];

    const int tid  = threadIdx.x;
    const int row0 = qt * 128;
    const int lr = tid >> 1;               // 0..127 (attn q-row)
    const int lc = (tid & 1) * 8;          // 0 or 8 (attn k-col)
    const int vr = tid >> 4;               // 0..15  (V k-row)
    const int vc = (tid & 15) * 4;         // 0..60  (V dk-col)
    const int tx = tid & 15, ty = tid >> 4;

    float acc[8][4];
    #pragma unroll
    for (int i = 0; i < 8; i++)
        #pragma unroll
        for (int j = 0; j < 4; j++) acc[i][j] = 0.f;

    const int kend = (qt + 1) * 128;       // causal bound (rows beyond q hold zeros)
    for (int kt = 0; kt < kend; kt += 16) {
        float4 a0 = *(const float4*)(Ah + (size_t)(row0 + lr) * CS + kt + lc);
        float4 a1 = *(const float4*)(Ah + (size_t)(row0 + lr) * CS + kt + lc + 4);
        As[lc+0][lr] = a0.x; As[lc+1][lr] = a0.y; As[lc+2][lr] = a0.z; As[lc+3][lr] = a0.w;
        As[lc+4][lr] = a1.x; As[lc+5][lr] = a1.y; As[lc+6][lr] = a1.z; As[lc+7][lr] = a1.w;
        float4 vv = *(const float4*)(Vh + (size_t)(kt + vr) * CDK + vc);
        Vs[vr][vc+0] = vv.x; Vs[vr][vc+1] = vv.y; Vs[vr][vc+2] = vv.z; Vs[vr][vc+3] = vv.w;
        __syncthreads();
        #pragma unroll
        for (int kk = 0; kk < 16; kk++) {
            float ra[8], rb[4];
            #pragma unroll
            for (int i = 0; i < 8; i++) ra[i] = As[kk][ty*8 + i];
            #pragma unroll
            for (int j = 0; j < 4; j++) rb[j] = Vs[kk][tx*4 + j];
            #pragma unroll
            for (int i = 0; i < 8; i++)
                #pragma unroll
                for (int j = 0; j < 4; j++) acc[i][j] += ra[i] * rb[j];
        }
        __syncthreads();
    }

    const int b = z >> 4, h = z & (CH - 1);
    #pragma unroll
    for (int i = 0; i < 8; i++) {
        int q = row0 + ty*8 + i;
        #pragma unroll
        for (int j = 0; j < 4; j++) {
            int dk = tx*4 + j;
            g_ctx[(((size_t)b*CS + q)*CH + h)*CDK + dk] = acc[i][j];
        }
    }
}

// ---------------------------------------------------------------------------
// Kernel 5: output projection.  out[m,n] = sum_k ctx[m,k]*Wo[n,k] + bias[n]
// ---------------------------------------------------------------------------
__global__ __launch_bounds__(256) void outproj_kernel(
    const float* __restrict__ W, const float* __restrict__ bias, float* __restrict__ Out)
{
    const int K = CD;
    __shared__ float As[8][128];
    __shared__ float Bs[8][128];

    const int tid  = threadIdx.x;
    const int row0 = blockIdx.y * 128;
    const int col0 = blockIdx.x * 128;
    const int lr = tid >> 1;
    const int lc = (tid & 1) * 4;
    const int tx = tid & 15, ty = tid >> 4;

    float acc[8][8];
    #pragma unroll
    for (int i = 0; i < 8; i++)
        #pragma unroll
        for (int j = 0; j < 8; j++) acc[i][j] = 0.f;

    for (int k0 = 0; k0 < K; k0 += 8) {
        float4 av = *(const float4*)(g_ctx + (size_t)(row0 + lr) * K + k0 + lc);
        float4 wv = *(const float4*)(W + (size_t)(col0 + lr) * K + k0 + lc);
        As[lc+0][lr] = av.x; As[lc+1][lr] = av.y; As[lc+2][lr] = av.z; As[lc+3][lr] = av.w;
        Bs[lc+0][lr] = wv.x; Bs[lc+1][lr] = wv.y; Bs[lc+2][lr] = wv.z; Bs[lc+3][lr] = wv.w;
        __syncthreads();
        #pragma unroll
        for (int kk = 0; kk < 8; kk++) {
            float ra[8], rb[8];
            #pragma unroll
            for (int i = 0; i < 8; i++) ra[i] = As[kk][ty*8 + i];
            #pragma unroll
            for (int j = 0; j < 8; j++) rb[j] = Bs[kk][tx*8 + j];
            #pragma unroll
            for (int i = 0; i < 8; i++)
                #pragma unroll
                for (int j = 0; j < 8; j++) acc[i][j] += ra[i] * rb[j];
        }
        __syncthreads();
    }

    #pragma unroll
    for (int i = 0; i < 8; i++) {
        int m = row0 + ty*8 + i;
        #pragma unroll
        for (int j = 0; j < 8; j++) {
            int n = col0 + tx*8 + j;
            Out[(size_t)m * CD + n] = acc[i][j] + bias[n];
        }
    }
}

// ---------------------------------------------------------------------------
extern "C" void kernel_launch(void* const* d_in, const int* in_sizes, int n_in,
                              void* d_out, int out_size)
{
    const float* query = (const float*)d_in[0];
    const float* key   = (const float*)d_in[1];
    const float* value = (const float*)d_in[2];
    // d_in[3] = mask (causal by construction; unused)
    const float* w_q = (const float*)d_in[4];
    const float* w_k = (const float*)d_in[5];
    const float* w_v = (const float*)d_in[6];
    const float* w_o = (const float*)d_in[7];
    const float* b_o = (const float*)d_in[8];

    float* out = (float*)d_out;
    const int attn_in_out = ((size_t)out_size >= OUT_ELEMS + ATTN_ELEMS) ? 1 : 0;
    float* attn_ptr = attn_in_out ? (out + OUT_ELEMS) : nullptr;
    const int use_internal = attn_in_out ? 0 : 1;

    // 1. Q/K/V projections (fused over grid.z)
    proj_kernel<<<dim3(CD/128, CM/128, 3), 256>>>(query, key, value, w_q, w_k, w_v);

    // 2. causal scores
    scores_kernel<<<dim3(CS/128, CS/128, CB*CH), 256>>>(attn_ptr, use_internal);

    // 3. softmax rows (writes final attention_weights incl. zeros)
    softmax_kernel<<<CB*CH*CS, 256>>>(attn_ptr, use_internal);

    // 4. context = attn @ V
    context_kernel<<<dim3(CS/128, CB*CH), 256>>>(attn_ptr, use_internal);

    // 5. output projection + bias
    outproj_kernel<<<dim3(CD/128, CM/128), 256>>>(w_o, b_o, out);
}

// round 10
// speedup vs baseline: 2.2116x; 2.2116x over previous
#include <cuda_runtime.h>
#include <cuda_bf16.h>
#include <stdint.h>

// Problem constants
#define CB 2
#define CS 2048
#define CD 1024
#define CH 16
#define CDK 64
#define CM (CB*CS)            // 4096 rows in the projection GEMMs

static const size_t OUT_ELEMS  = (size_t)CB*CS*CD;       // 4,194,304
static const size_t ATTN_ELEMS = (size_t)CB*CH*CS*CS;    // 134,217,728

// Scratch (device globals: allocation-free rule)
__device__ float g_Q[(size_t)CB*CH*CS*CDK];
__device__ float g_K[(size_t)CB*CH*CS*CDK];
__device__ float g_V[(size_t)CB*CH*CS*CDK];
__device__ float g_ctx[(size_t)CB*CS*CD];
__device__ float g_attn[(size_t)CB*CH*CS*CS];   // fallback if d_out doesn't hold attn

// ===========================================================================
// mma.sync bf16 helpers (baseline PTX — legal on compute_103 virtual arch)
// ===========================================================================
__device__ __forceinline__ uint32_t bf2u(__nv_bfloat162 v) { return *reinterpret_cast<uint32_t*>(&v); }

__device__ __forceinline__ void mma16816(float* c, const uint32_t* a, const uint32_t* b) {
    asm volatile(
        "mma.sync.aligned.m16n8k16.row.col.f32.bf16.bf16.f32 "
        "{%0,%1,%2,%3}, {%4,%5,%6,%7}, {%8,%9}, {%0,%1,%2,%3};"
        : "+f"(c[0]), "+f"(c[1]), "+f"(c[2]), "+f"(c[3])
        : "r"(a[0]), "r"(a[1]), "r"(a[2]), "r"(a[3]), "r"(b[0]), "r"(b[1]));
}

// split fp32 -> (hi, lo) bf16 pairs, packed as 2x uint32 each
__device__ __forceinline__ void split4(float4 v, uint2& hi, uint2& lo) {
    __nv_bfloat16 h0 = __float2bfloat16_rn(v.x);
    __nv_bfloat16 h1 = __float2bfloat16_rn(v.y);
    __nv_bfloat16 h2 = __float2bfloat16_rn(v.z);
    __nv_bfloat16 h3 = __float2bfloat16_rn(v.w);
    float l0 = v.x - __bfloat162float(h0);
    float l1 = v.y - __bfloat162float(h1);
    float l2 = v.z - __bfloat162float(h2);
    float l3 = v.w - __bfloat162float(h3);
    hi = make_uint2(bf2u(__halves2bfloat162(h0, h1)), bf2u(__halves2bfloat162(h2, h3)));
    lo = make_uint2(bf2u(__halves2bfloat162(__float2bfloat16_rn(l0), __float2bfloat16_rn(l1))),
                    bf2u(__halves2bfloat162(__float2bfloat16_rn(l2), __float2bfloat16_rn(l3))));
}

// ===========================================================================
// Split-bf16 mma.sync GEMM core: acc[128,128] = A[128,1024] * B[128,1024]^T
// Block 128x128, BK=32, 8 warps in 2x4 grid, warp tile 64x32.
// SMEM rows padded to 40 bf16 (20 words) -> conflict-free LDS.32 fragments.
// ===========================================================================
#define PADK 40

__device__ __forceinline__ void mma_gemm_core(
    const float* __restrict__ Abase, const float* __restrict__ Bbase,
    __nv_bfloat16* Ahi, __nv_bfloat16* Alo, __nv_bfloat16* Bhi, __nv_bfloat16* Blo,
    float acc[4][4][4])
{
    const int tid  = threadIdx.x;
    const int wid  = tid >> 5, lane = tid & 31;
    const int wm   = wid & 1,  wn   = wid >> 1;     // warp grid 2x4
    const int quad = lane >> 2, tq  = lane & 3;

    const int lrow = tid >> 1;           // 0..127 : tile row loaded by this thread
    const int lk   = (tid & 1) * 16;     // 0 / 16 : k-half within BK=32

    const float* arow = Abase + (size_t)lrow * CD;
    const float* brow = Bbase + (size_t)lrow * CD;

    #pragma unroll
    for (int mi = 0; mi < 4; mi++)
        #pragma unroll
        for (int ni = 0; ni < 4; ni++)
            #pragma unroll
            for (int r = 0; r < 4; r++) acc[mi][ni][r] = 0.f;

    for (int c = 0; c < CD / 32; c++) {
        // Prefetch fp32 to registers (overlaps previous chunk's MMAs)
        float4 av[4], bv[4];
        #pragma unroll
        for (int i = 0; i < 4; i++) {
            av[i] = *(const float4*)(arow + c * 32 + lk + i * 4);
            bv[i] = *(const float4*)(brow + c * 32 + lk + i * 4);
        }
        __syncthreads();   // previous chunk's fragment reads complete

        #pragma unroll
        for (int i = 0; i < 4; i++) {
            uint2 hi, lo;
            split4(av[i], hi, lo);
            *(uint2*)(Ahi + lrow * PADK + lk + i * 4) = hi;
            *(uint2*)(Alo + lrow * PADK + lk + i * 4) = lo;
            split4(bv[i], hi, lo);
            *(uint2*)(Bhi + lrow * PADK + lk + i * 4) = hi;
            *(uint2*)(Blo + lrow * PADK + lk + i * 4) = lo;
        }
        __syncthreads();

        #pragma unroll
        for (int k0 = 0; k0 < 32; k0 += 16) {
            uint32_t ah[4][4], al[4][4], bh[4][2], bl[4][2];
            #pragma unroll
            for (int mi = 0; mi < 4; mi++) {
                const int r0 = wm * 64 + mi * 16 + quad;
                const __nv_bfloat16* p = Ahi + r0 * PADK + k0 + tq * 2;
                const __nv_bfloat16* q = Alo + r0 * PADK + k0 + tq * 2;
                ah[mi][0] = *(const uint32_t*)p;
                ah[mi][1] = *(const uint32_t*)(p + 8 * PADK);
                ah[mi][2] = *(const uint32_t*)(p + 8);
                ah[mi][3] = *(const uint32_t*)(p + 8 * PADK + 8);
                al[mi][0] = *(const uint32_t*)q;
                al[mi][1] = *(const uint32_t*)(q + 8 * PADK);
                al[mi][2] = *(const uint32_t*)(q + 8);
                al[mi][3] = *(const uint32_t*)(q + 8 * PADK + 8);
            }
            #pragma unroll
            for (int ni = 0; ni < 4; ni++) {
                const int n0 = wn * 32 + ni * 8 + quad;
                const __nv_bfloat16* p = Bhi + n0 * PADK + k0 + tq * 2;
                const __nv_bfloat16* q = Blo + n0 * PADK + k0 + tq * 2;
                bh[ni][0] = *(const uint32_t*)p;
                bh[ni][1] = *(const uint32_t*)(p + 8);
                bl[ni][0] = *(const uint32_t*)q;
                bl[ni][1] = *(const uint32_t*)(q + 8);
            }
            // 3 passes; same-acc HMMAs are 16 instructions apart (no RAW stall)
            #pragma unroll
            for (int mi = 0; mi < 4; mi++)
                #pragma unroll
                for (int ni = 0; ni < 4; ni++) mma16816(acc[mi][ni], ah[mi], bh[ni]);
            #pragma unroll
            for (int mi = 0; mi < 4; mi++)
                #pragma unroll
                for (int ni = 0; ni < 4; ni++) mma16816(acc[mi][ni], al[mi], bh[ni]);
            #pragma unroll
            for (int mi = 0; mi < 4; mi++)
                #pragma unroll
                for (int ni = 0; ni < 4; ni++) mma16816(acc[mi][ni], ah[mi], bl[ni]);
        }
    }
}

// ---------------------------------------------------------------------------
// Kernel 1: Q/K/V projections via mma.sync.  Stores [b,h,s,dk] layout.
// ---------------------------------------------------------------------------
__global__ __launch_bounds__(256) void proj_mma(
    const float* __restrict__ Xq, const float* __restrict__ Xk, const float* __restrict__ Xv,
    const float* __restrict__ Wq, const float* __restrict__ Wk, const float* __restrict__ Wv)
{
    __shared__ __nv_bfloat16 Ahi[128 * PADK], Alo[128 * PADK];
    __shared__ __nv_bfloat16 Bhi[128 * PADK], Blo[128 * PADK];

    const int z = blockIdx.z;
    const float* A = (z == 0) ? Xq : (z == 1) ? Xk : Xv;
    const float* W = (z == 0) ? Wq : (z == 1) ? Wk : Wv;
    float* Out     = (z == 0) ? g_Q : (z == 1) ? g_K : g_V;

    const int row0 = blockIdx.y * 128, col0 = blockIdx.x * 128;
    float acc[4][4][4];
    mma_gemm_core(A + (size_t)row0 * CD, W + (size_t)col0 * CD, Ahi, Alo, Bhi, Blo, acc);

    const int wid  = threadIdx.x >> 5, lane = threadIdx.x & 31;
    const int wm   = wid & 1, wn = wid >> 1;
    const int quad = lane >> 2, tq = lane & 3;

    #pragma unroll
    for (int mi = 0; mi < 4; mi++) {
        const int m = row0 + wm * 64 + mi * 16 + quad;
        const int b = m >> 11, s = m & (CS - 1);
        #pragma unroll
        for (int ni = 0; ni < 4; ni++) {
            const int n  = col0 + wn * 32 + ni * 8 + tq * 2;
            const int h  = n >> 6, dk = n & (CDK - 1);
            float* o0 = &Out[(((size_t)(b * CH + h)) * CS + s)     * CDK + dk];
            float* o1 = &Out[(((size_t)(b * CH + h)) * CS + s + 8) * CDK + dk];
            *(float2*)o0 = make_float2(acc[mi][ni][0], acc[mi][ni][1]);
            *(float2*)o1 = make_float2(acc[mi][ni][2], acc[mi][ni][3]);
        }
    }
}

// ---------------------------------------------------------------------------
// Kernel 5: output projection via mma.sync.  out = ctx @ Wo^T + bias.
// ---------------------------------------------------------------------------
__global__ __launch_bounds__(256) void outproj_mma(
    const float* __restrict__ W, const float* __restrict__ bias, float* __restrict__ Out)
{
    __shared__ __nv_bfloat16 Ahi[128 * PADK], Alo[128 * PADK];
    __shared__ __nv_bfloat16 Bhi[128 * PADK], Blo[128 * PADK];

    const int row0 = blockIdx.y * 128, col0 = blockIdx.x * 128;
    float acc[4][4][4];
    mma_gemm_core(g_ctx + (size_t)row0 * CD, W + (size_t)col0 * CD, Ahi, Alo, Bhi, Blo, acc);

    const int wid  = threadIdx.x >> 5, lane = threadIdx.x & 31;
    const int wm   = wid & 1, wn = wid >> 1;
    const int quad = lane >> 2, tq = lane & 3;

    #pragma unroll
    for (int mi = 0; mi < 4; mi++) {
        const int m = row0 + wm * 64 + mi * 16 + quad;
        #pragma unroll
        for (int ni = 0; ni < 4; ni++) {
            const int n = col0 + wn * 32 + ni * 8 + tq * 2;
            const float2 bv = *(const float2*)(bias + n);
            *(float2*)&Out[(size_t)m * CD + n] =
                make_float2(acc[mi][ni][0] + bv.x, acc[mi][ni][1] + bv.y);
            *(float2*)&Out[(size_t)(m + 8) * CD + n] =
                make_float2(acc[mi][ni][2] + bv.x, acc[mi][ni][3] + bv.y);
        }
    }
}

// ---------------------------------------------------------------------------
// Kernel 2: scores = scale * Q @ K^T (causal).  (unchanged FFMA)
// ---------------------------------------------------------------------------
__global__ __launch_bounds__(256) void scores_kernel(float* __restrict__ attn_out, int use_internal)
{
    if (blockIdx.x > blockIdx.y) return;
    float* attn = use_internal ? g_attn : attn_out;

    const int z = blockIdx.z;
    const float* Qh = g_Q + (size_t)z * CS * CDK;
    const float* Kh = g_K + (size_t)z * CS * CDK;

    __shared__ float As[8][128];
    __shared__ float Bs[8][128];

    const int tid  = threadIdx.x;
    const int row0 = blockIdx.y * 128;
    const int col0 = blockIdx.x * 128;
    const int lr = tid >> 1;
    const int lc = (tid & 1) * 4;
    const int tx = tid & 15, ty = tid >> 4;

    float acc[8][8];
    #pragma unroll
    for (int i = 0; i < 8; i++)
        #pragma unroll
        for (int j = 0; j < 8; j++) acc[i][j] = 0.f;

    for (int k0 = 0; k0 < CDK; k0 += 8) {
        float4 av = *(const float4*)(Qh + (size_t)(row0 + lr) * CDK + k0 + lc);
        float4 wv = *(const float4*)(Kh + (size_t)(col0 + lr) * CDK + k0 + lc);
        As[lc+0][lr] = av.x; As[lc+1][lr] = av.y; As[lc+2][lr] = av.z; As[lc+3][lr] = av.w;
        Bs[lc+0][lr] = wv.x; Bs[lc+1][lr] = wv.y; Bs[lc+2][lr] = wv.z; Bs[lc+3][lr] = wv.w;
        __syncthreads();
        #pragma unroll
        for (int kk = 0; kk < 8; kk++) {
            float ra[8], rb[8];
            #pragma unroll
            for (int i = 0; i < 8; i++) ra[i] = As[kk][ty*8 + i];
            #pragma unroll
            for (int j = 0; j < 8; j++) rb[j] = Bs[kk][tx*8 + j];
            #pragma unroll
            for (int i = 0; i < 8; i++)
                #pragma unroll
                for (int j = 0; j < 8; j++) acc[i][j] += ra[i] * rb[j];
        }
        __syncthreads();
    }

    const float scale = 0.125f;
    #pragma unroll
    for (int i = 0; i < 8; i++) {
        int q = row0 + ty*8 + i;
        #pragma unroll
        for (int j = 0; j < 8; j++) {
            int k = col0 + tx*8 + j;
            if (k <= q)
                attn[((size_t)z * CS + q) * CS + k] = acc[i][j] * scale;
        }
    }
}

// ---------------------------------------------------------------------------
// Kernel 3: row softmax.  (unchanged)
// ---------------------------------------------------------------------------
__global__ __launch_bounds__(256) void softmax_kernel(float* __restrict__ attn_out, int use_internal)
{
    float* attn = use_internal ? g_attn : attn_out;
    __shared__ float row[CS];
    __shared__ float red[8];

    const int r   = blockIdx.x;
    const int q   = r & (CS - 1);
    const size_t base = (size_t)r * CS;
    const int len = q + 1;
    const int tid = threadIdx.x;

    float m = -1e30f;
    for (int i = tid; i < len; i += 256) {
        float v = attn[base + i];
        row[i] = v;
        m = fmaxf(m, v);
    }
    #pragma unroll
    for (int o = 16; o; o >>= 1) m = fmaxf(m, __shfl_xor_sync(0xffffffffu, m, o));
    if ((tid & 31) == 0) red[tid >> 5] = m;
    __syncthreads();
    m = red[0];
    #pragma unroll
    for (int i = 1; i < 8; i++) m = fmaxf(m, red[i]);
    __syncthreads();

    float s = 0.f;
    for (int i = tid; i < len; i += 256) {
        float e = __expf(row[i] - m);
        row[i] = e;
        s += e;
    }
    #pragma unroll
    for (int o = 16; o; o >>= 1) s += __shfl_xor_sync(0xffffffffu, s, o);
    if ((tid & 31) == 0) red[tid >> 5] = s;
    __syncthreads();
    s = red[0];
    #pragma unroll
    for (int i = 1; i < 8; i++) s += red[i];

    const float inv = 1.f / s;
    for (int i = tid; i < len; i += 256) attn[base + i] = row[i] * inv;
    for (int i = len + tid; i < CS; i += 256) attn[base + i] = 0.f;
}

// ---------------------------------------------------------------------------
// Kernel 4: context = attn @ V.  (unchanged FFMA)
// ---------------------------------------------------------------------------
__global__ __launch_bounds__(256) void context_kernel(const float* __restrict__ attn_in, int use_internal)
{
    const float* attn = use_internal ? g_attn : attn_in;
    const int z  = blockIdx.y;
    const int qt = blockIdx.x;
    const float* Ah = attn + (size_t)z * CS * CS;
    const float* Vh = g_V  + (size_t)z * CS * CDK;

    __shared__ float As[16][128];
    __shared__ float Vs[16][64];

    const int tid  = threadIdx.x;
    const int row0 = qt * 128;
    const int lr = tid >> 1;
    const int lc = (tid & 1) * 8;
    const int vr = tid >> 4;
    const int vc = (tid & 15) * 4;
    const int tx = tid & 15, ty = tid >> 4;

    float acc[8][4];
    #pragma unroll
    for (int i = 0; i < 8; i++)
        #pragma unroll
        for (int j = 0; j < 4; j++) acc[i][j] = 0.f;

    const int kend = (qt + 1) * 128;
    for (int kt = 0; kt < kend; kt += 16) {
        float4 a0 = *(const float4*)(Ah + (size_t)(row0 + lr) * CS + kt + lc);
        float4 a1 = *(const float4*)(Ah + (size_t)(row0 + lr) * CS + kt + lc + 4);
        As[lc+0][lr] = a0.x; As[lc+1][lr] = a0.y; As[lc+2][lr] = a0.z; As[lc+3][lr] = a0.w;
        As[lc+4][lr] = a1.x; As[lc+5][lr] = a1.y; As[lc+6][lr] = a1.z; As[lc+7][lr] = a1.w;
        float4 vv = *(const float4*)(Vh + (size_t)(kt + vr) * CDK + vc);
        Vs[vr][vc+0] = vv.x; Vs[vr][vc+1] = vv.y; Vs[vr][vc+2] = vv.z; Vs[vr][vc+3] = vv.w;
        __syncthreads();
        #pragma unroll
        for (int kk = 0; kk < 16; kk++) {
            float ra[8], rb[4];
            #pragma unroll
            for (int i = 0; i < 8; i++) ra[i] = As[kk][ty*8 + i];
            #pragma unroll
            for (int j = 0; j < 4; j++) rb[j] = Vs[kk][tx*4 + j];
            #pragma unroll
            for (int i = 0; i < 8; i++)
                #pragma unroll
                for (int j = 0; j < 4; j++) acc[i][j] += ra[i] * rb[j];
        }
        __syncthreads();
    }

    const int b = z >> 4, h = z & (CH - 1);
    #pragma unroll
    for (int i = 0; i < 8; i++) {
        int q = row0 + ty*8 + i;
        #pragma unroll
        for (int j = 0; j < 4; j++) {
            int dk = tx*4 + j;
            g_ctx[(((size_t)b*CS + q)*CH + h)*CDK + dk] = acc[i][j];
        }
    }
}

// ---------------------------------------------------------------------------
extern "C" void kernel_launch(void* const* d_in, const int* in_sizes, int n_in,
                              void* d_out, int out_size)
{
    const float* query = (const float*)d_in[0];
    const float* key   = (const float*)d_in[1];
    const float* value = (const float*)d_in[2];
    // d_in[3] = mask (causal by construction; unused)
    const float* w_q = (const float*)d_in[4];
    const float* w_k = (const float*)d_in[5];
    const float* w_v = (const float*)d_in[6];
    const float* w_o = (const float*)d_in[7];
    const float* b_o = (const float*)d_in[8];

    float* out = (float*)d_out;
    const int attn_in_out = ((size_t)out_size >= OUT_ELEMS + ATTN_ELEMS) ? 1 : 0;
    float* attn_ptr = attn_in_out ? (out + OUT_ELEMS) : nullptr;
    const int use_internal = attn_in_out ? 0 : 1;

    // 1. Q/K/V projections (mma.sync split-bf16)
    proj_mma<<<dim3(CD/128, CM/128, 3), 256>>>(query, key, value, w_q, w_k, w_v);

    // 2. causal scores
    scores_kernel<<<dim3(CS/128, CS/128, CB*CH), 256>>>(attn_ptr, use_internal);

    // 3. softmax rows (writes final attention_weights incl. zeros)
    softmax_kernel<<<CB*CH*CS, 256>>>(attn_ptr, use_internal);

    // 4. context = attn @ V
    context_kernel<<<dim3(CS/128, CB*CH), 256>>>(attn_ptr, use_internal);

    // 5. output projection + bias (mma.sync split-bf16)
    outproj_mma<<<dim3(CD/128, CM/128), 256>>>(w_o, b_o, out);
}

// round 11
// speedup vs baseline: 3.1465x; 1.4227x over previous
#include <cuda_runtime.h>
#include <cuda_bf16.h>
#include <stdint.h>

// Problem constants
#define CB 2
#define CS 2048
#define CD 1024
#define CH 16
#define CDK 64
#define CM (CB*CS)            // 4096 rows in the projection GEMMs

static const size_t OUT_ELEMS  = (size_t)CB*CS*CD;       // 4,194,304
static const size_t ATTN_ELEMS = (size_t)CB*CH*CS*CS;    // 134,217,728

// Scratch (device globals: allocation-free rule)
__device__ float g_Q[(size_t)CB*CH*CS*CDK];
__device__ float g_K[(size_t)CB*CH*CS*CDK];
__device__ float g_V[(size_t)CB*CH*CS*CDK];
__device__ float g_ctx[(size_t)CB*CS*CD];
__device__ float g_attn[(size_t)CB*CH*CS*CS];   // fallback if d_out doesn't hold attn

// ===========================================================================
// mma.sync bf16 helpers (baseline PTX — legal on compute_103 virtual arch)
// ===========================================================================
__device__ __forceinline__ uint32_t bf2u(__nv_bfloat162 v) { return *reinterpret_cast<uint32_t*>(&v); }

__device__ __forceinline__ void mma16816(float* c, const uint32_t* a, const uint32_t* b) {
    asm volatile(
        "mma.sync.aligned.m16n8k16.row.col.f32.bf16.bf16.f32 "
        "{%0,%1,%2,%3}, {%4,%5,%6,%7}, {%8,%9}, {%0,%1,%2,%3};"
        : "+f"(c[0]), "+f"(c[1]), "+f"(c[2]), "+f"(c[3])
        : "r"(a[0]), "r"(a[1]), "r"(a[2]), "r"(a[3]), "r"(b[0]), "r"(b[1]));
}

// split fp32 -> (hi, lo) bf16 pairs, packed as 2x uint32 each
__device__ __forceinline__ void split4(float4 v, uint2& hi, uint2& lo) {
    __nv_bfloat16 h0 = __float2bfloat16_rn(v.x);
    __nv_bfloat16 h1 = __float2bfloat16_rn(v.y);
    __nv_bfloat16 h2 = __float2bfloat16_rn(v.z);
    __nv_bfloat16 h3 = __float2bfloat16_rn(v.w);
    float l0 = v.x - __bfloat162float(h0);
    float l1 = v.y - __bfloat162float(h1);
    float l2 = v.z - __bfloat162float(h2);
    float l3 = v.w - __bfloat162float(h3);
    hi = make_uint2(bf2u(__halves2bfloat162(h0, h1)), bf2u(__halves2bfloat162(h2, h3)));
    lo = make_uint2(bf2u(__halves2bfloat162(__float2bfloat16_rn(l0), __float2bfloat16_rn(l1))),
                    bf2u(__halves2bfloat162(__float2bfloat16_rn(l2), __float2bfloat16_rn(l3))));
}
__device__ __forceinline__ void split1(float v, __nv_bfloat16& hi, __nv_bfloat16& lo) {
    hi = __float2bfloat16_rn(v);
    lo = __float2bfloat16_rn(v - __bfloat162float(hi));
}

// ===========================================================================
// Split-bf16 mma.sync GEMM core: acc[128,128] = A[128,K] * B[128,K]^T
// Block 128x128, BK=32, 8 warps in 2x4 grid, warp tile 64x32.
// SMEM rows padded to 40 bf16 (20 words) -> conflict-free LDS.32 fragments.
// ===========================================================================
#define PADK 40

__device__ __forceinline__ void mma_gemm_core(
    const float* __restrict__ Abase, const float* __restrict__ Bbase,
    int ld, int kTotal,
    __nv_bfloat16* Ahi, __nv_bfloat16* Alo, __nv_bfloat16* Bhi, __nv_bfloat16* Blo,
    float acc[4][4][4])
{
    const int tid  = threadIdx.x;
    const int wid  = tid >> 5, lane = tid & 31;
    const int wm   = wid & 1,  wn   = wid >> 1;     // warp grid 2x4
    const int quad = lane >> 2, tq  = lane & 3;

    const int lrow = tid >> 1;           // 0..127 : tile row loaded by this thread
    const int lk   = (tid & 1) * 16;     // 0 / 16 : k-half within BK=32

    const float* arow = Abase + (size_t)lrow * ld;
    const float* brow = Bbase + (size_t)lrow * ld;

    #pragma unroll
    for (int mi = 0; mi < 4; mi++)
        #pragma unroll
        for (int ni = 0; ni < 4; ni++)
            #pragma unroll
            for (int r = 0; r < 4; r++) acc[mi][ni][r] = 0.f;

    for (int c = 0; c < kTotal / 32; c++) {
        // Prefetch fp32 to registers (overlaps previous chunk's MMAs)
        float4 av[4], bv[4];
        #pragma unroll
        for (int i = 0; i < 4; i++) {
            av[i] = *(const float4*)(arow + c * 32 + lk + i * 4);
            bv[i] = *(const float4*)(brow + c * 32 + lk + i * 4);
        }
        __syncthreads();   // previous chunk's fragment reads complete

        #pragma unroll
        for (int i = 0; i < 4; i++) {
            uint2 hi, lo;
            split4(av[i], hi, lo);
            *(uint2*)(Ahi + lrow * PADK + lk + i * 4) = hi;
            *(uint2*)(Alo + lrow * PADK + lk + i * 4) = lo;
            split4(bv[i], hi, lo);
            *(uint2*)(Bhi + lrow * PADK + lk + i * 4) = hi;
            *(uint2*)(Blo + lrow * PADK + lk + i * 4) = lo;
        }
        __syncthreads();

        #pragma unroll
        for (int k0 = 0; k0 < 32; k0 += 16) {
            uint32_t ah[4][4], al[4][4], bh[4][2], bl[4][2];
            #pragma unroll
            for (int mi = 0; mi < 4; mi++) {
                const int r0 = wm * 64 + mi * 16 + quad;
                const __nv_bfloat16* p = Ahi + r0 * PADK + k0 + tq * 2;
                const __nv_bfloat16* q = Alo + r0 * PADK + k0 + tq * 2;
                ah[mi][0] = *(const uint32_t*)p;
                ah[mi][1] = *(const uint32_t*)(p + 8 * PADK);
                ah[mi][2] = *(const uint32_t*)(p + 8);
                ah[mi][3] = *(const uint32_t*)(p + 8 * PADK + 8);
                al[mi][0] = *(const uint32_t*)q;
                al[mi][1] = *(const uint32_t*)(q + 8 * PADK);
                al[mi][2] = *(const uint32_t*)(q + 8);
                al[mi][3] = *(const uint32_t*)(q + 8 * PADK + 8);
            }
            #pragma unroll
            for (int ni = 0; ni < 4; ni++) {
                const int n0 = wn * 32 + ni * 8 + quad;
                const __nv_bfloat16* p = Bhi + n0 * PADK + k0 + tq * 2;
                const __nv_bfloat16* q = Blo + n0 * PADK + k0 + tq * 2;
                bh[ni][0] = *(const uint32_t*)p;
                bh[ni][1] = *(const uint32_t*)(p + 8);
                bl[ni][0] = *(const uint32_t*)q;
                bl[ni][1] = *(const uint32_t*)(q + 8);
            }
            // 3 passes; same-acc HMMAs are 16 instructions apart (no RAW stall)
            #pragma unroll
            for (int mi = 0; mi < 4; mi++)
                #pragma unroll
                for (int ni = 0; ni < 4; ni++) mma16816(acc[mi][ni], ah[mi], bh[ni]);
            #pragma unroll
            for (int mi = 0; mi < 4; mi++)
                #pragma unroll
                for (int ni = 0; ni < 4; ni++) mma16816(acc[mi][ni], al[mi], bh[ni]);
            #pragma unroll
            for (int mi = 0; mi < 4; mi++)
                #pragma unroll
                for (int ni = 0; ni < 4; ni++) mma16816(acc[mi][ni], ah[mi], bl[ni]);
        }
    }
}

// ---------------------------------------------------------------------------
// Kernel 1: Q/K/V projections via mma.sync.  Stores [b,h,s,dk] layout.
// ---------------------------------------------------------------------------
__global__ __launch_bounds__(256) void proj_mma(
    const float* __restrict__ Xq, const float* __restrict__ Xk, const float* __restrict__ Xv,
    const float* __restrict__ Wq, const float* __restrict__ Wk, const float* __restrict__ Wv)
{
    __shared__ __nv_bfloat16 Ahi[128 * PADK], Alo[128 * PADK];
    __shared__ __nv_bfloat16 Bhi[128 * PADK], Blo[128 * PADK];

    const int z = blockIdx.z;
    const float* A = (z == 0) ? Xq : (z == 1) ? Xk : Xv;
    const float* W = (z == 0) ? Wq : (z == 1) ? Wk : Wv;
    float* Out     = (z == 0) ? g_Q : (z == 1) ? g_K : g_V;

    const int row0 = blockIdx.y * 128, col0 = blockIdx.x * 128;
    float acc[4][4][4];
    mma_gemm_core(A + (size_t)row0 * CD, W + (size_t)col0 * CD, CD, CD, Ahi, Alo, Bhi, Blo, acc);

    const int wid  = threadIdx.x >> 5, lane = threadIdx.x & 31;
    const int wm   = wid & 1, wn = wid >> 1;
    const int quad = lane >> 2, tq = lane & 3;

    #pragma unroll
    for (int mi = 0; mi < 4; mi++) {
        const int m = row0 + wm * 64 + mi * 16 + quad;
        const int b = m >> 11, s = m & (CS - 1);
        #pragma unroll
        for (int ni = 0; ni < 4; ni++) {
            const int n  = col0 + wn * 32 + ni * 8 + tq * 2;
            const int h  = n >> 6, dk = n & (CDK - 1);
            float* o0 = &Out[(((size_t)(b * CH + h)) * CS + s)     * CDK + dk];
            float* o1 = &Out[(((size_t)(b * CH + h)) * CS + s + 8) * CDK + dk];
            *(float2*)o0 = make_float2(acc[mi][ni][0], acc[mi][ni][1]);
            *(float2*)o1 = make_float2(acc[mi][ni][2], acc[mi][ni][3]);
        }
    }
}

// ---------------------------------------------------------------------------
// Kernel 5: output projection via mma.sync.  out = ctx @ Wo^T + bias.
// ---------------------------------------------------------------------------
__global__ __launch_bounds__(256) void outproj_mma(
    const float* __restrict__ W, const float* __restrict__ bias, float* __restrict__ Out)
{
    __shared__ __nv_bfloat16 Ahi[128 * PADK], Alo[128 * PADK];
    __shared__ __nv_bfloat16 Bhi[128 * PADK], Blo[128 * PADK];

    const int row0 = blockIdx.y * 128, col0 = blockIdx.x * 128;
    float acc[4][4][4];
    mma_gemm_core(g_ctx + (size_t)row0 * CD, W + (size_t)col0 * CD, CD, CD, Ahi, Alo, Bhi, Blo, acc);

    const int wid  = threadIdx.x >> 5, lane = threadIdx.x & 31;
    const int wm   = wid & 1, wn = wid >> 1;
    const int quad = lane >> 2, tq = lane & 3;

    #pragma unroll
    for (int mi = 0; mi < 4; mi++) {
        const int m = row0 + wm * 64 + mi * 16 + quad;
        #pragma unroll
        for (int ni = 0; ni < 4; ni++) {
            const int n = col0 + wn * 32 + ni * 8 + tq * 2;
            const float2 bv = *(const float2*)(bias + n);
            *(float2*)&Out[(size_t)m * CD + n] =
                make_float2(acc[mi][ni][0] + bv.x, acc[mi][ni][1] + bv.y);
            *(float2*)&Out[(size_t)(m + 8) * CD + n] =
                make_float2(acc[mi][ni][2] + bv.x, acc[mi][ni][3] + bv.y);
        }
    }
}

// ---------------------------------------------------------------------------
// Kernel 2 (NEW): scores = scale * Q @ K^T (causal) via mma.sync.
// ---------------------------------------------------------------------------
__global__ __launch_bounds__(256) void scores_mma(float* __restrict__ attn_out, int use_internal)
{
    if (blockIdx.x > blockIdx.y) return;   // tile fully above diagonal
    float* attn = use_internal ? g_attn : attn_out;

    __shared__ __nv_bfloat16 Ahi[128 * PADK], Alo[128 * PADK];
    __shared__ __nv_bfloat16 Bhi[128 * PADK], Blo[128 * PADK];

    const int z = blockIdx.z;
    const float* Qh = g_Q + (size_t)z * CS * CDK;
    const float* Kh = g_K + (size_t)z * CS * CDK;

    const int row0 = blockIdx.y * 128, col0 = blockIdx.x * 128;
    float acc[4][4][4];
    mma_gemm_core(Qh + (size_t)row0 * CDK, Kh + (size_t)col0 * CDK, CDK, CDK,
                  Ahi, Alo, Bhi, Blo, acc);

    const int wid  = threadIdx.x >> 5, lane = threadIdx.x & 31;
    const int wm   = wid & 1, wn = wid >> 1;
    const int quad = lane >> 2, tq = lane & 3;
    const float scale = 0.125f;

    #pragma unroll
    for (int mi = 0; mi < 4; mi++) {
        const int q0 = row0 + wm * 64 + mi * 16 + quad;
        #pragma unroll
        for (int ni = 0; ni < 4; ni++) {
            const int k = col0 + wn * 32 + ni * 8 + tq * 2;
            float* p0 = &attn[((size_t)z * CS + q0) * CS + k];
            float* p1 = &attn[((size_t)z * CS + q0 + 8) * CS + k];
            if (k + 1 <= q0)
                *(float2*)p0 = make_float2(acc[mi][ni][0] * scale, acc[mi][ni][1] * scale);
            else if (k <= q0)
                *p0 = acc[mi][ni][0] * scale;
            if (k + 1 <= q0 + 8)
                *(float2*)p1 = make_float2(acc[mi][ni][2] * scale, acc[mi][ni][3] * scale);
            else if (k <= q0 + 8)
                *p1 = acc[mi][ni][2] * scale;
        }
    }
}

// ---------------------------------------------------------------------------
// Kernel 3 (VECTORIZED): row softmax.  One block per (b,h,q) row.
// float4 loads/stores; zero-fill beyond causal edge folded into store pass.
// ---------------------------------------------------------------------------
__global__ __launch_bounds__(256) void softmax_kernel(float* __restrict__ attn_out, int use_internal)
{
    float* attn = use_internal ? g_attn : attn_out;
    __shared__ float4 row4[CS / 4];
    __shared__ float red[8];

    const int r   = blockIdx.x;
    const int q   = r & (CS - 1);
    const int len = q + 1;
    const int tid = threadIdx.x;
    float4* g4 = (float4*)(attn + (size_t)r * CS);

    // pass 1: load + max over valid lanes
    float m = -1e30f;
    for (int i4 = tid; i4 < CS / 4; i4 += 256) {
        const int i = i4 * 4;
        if (i < len) {
            float4 v = g4[i4];
            row4[i4] = v;
            m = fmaxf(m, v.x);
            if (i + 1 < len) m = fmaxf(m, v.y);
            if (i + 2 < len) m = fmaxf(m, v.z);
            if (i + 3 < len) m = fmaxf(m, v.w);
        }
    }
    #pragma unroll
    for (int o = 16; o; o >>= 1) m = fmaxf(m, __shfl_xor_sync(0xffffffffu, m, o));
    if ((tid & 31) == 0) red[tid >> 5] = m;
    __syncthreads();
    m = red[0];
    #pragma unroll
    for (int i = 1; i < 8; i++) m = fmaxf(m, red[i]);
    __syncthreads();

    // pass 2: exp + sum; invalid lanes forced to 0 in smem
    float s = 0.f;
    for (int i4 = tid; i4 < CS / 4; i4 += 256) {
        const int i = i4 * 4;
        float4 v;
        if (i + 3 < len) {
            v = row4[i4];
            v.x = __expf(v.x - m); v.y = __expf(v.y - m);
            v.z = __expf(v.z - m); v.w = __expf(v.w - m);
        } else if (i < len) {
            v = row4[i4];
            v.x = (i     < len) ? __expf(v.x - m) : 0.f;
            v.y = (i + 1 < len) ? __expf(v.y - m) : 0.f;
            v.z = (i + 2 < len) ? __expf(v.z - m) : 0.f;
            v.w = (i + 3 < len) ? __expf(v.w - m) : 0.f;
        } else {
            v = make_float4(0.f, 0.f, 0.f, 0.f);
        }
        row4[i4] = v;
        s += v.x + v.y + v.z + v.w;
    }
    #pragma unroll
    for (int o = 16; o; o >>= 1) s += __shfl_xor_sync(0xffffffffu, s, o);
    if ((tid & 31) == 0) red[tid >> 5] = s;
    __syncthreads();
    s = red[0];
    #pragma unroll
    for (int i = 1; i < 8; i++) s += red[i];

    // pass 3: normalize + store full row (zeros included)
    const float inv = 1.f / s;
    for (int i4 = tid; i4 < CS / 4; i4 += 256) {
        float4 v = row4[i4];
        g4[i4] = make_float4(v.x * inv, v.y * inv, v.z * inv, v.w * inv);
    }
}

// ---------------------------------------------------------------------------
// Kernel 4 (NEW): context = attn @ V via mma.sync (split-bf16).
// Per (b,h): M=128 q-rows per block, N=64 (DK), K bounded by causal edge.
// V chunk transposed on smem store so B is [dk][k] (col layout for row.col).
// Warp grid 4x2, warp tile 32x32.
// ---------------------------------------------------------------------------
__global__ __launch_bounds__(256) void context_mma(const float* __restrict__ attn_in, int use_internal)
{
    const float* attn = use_internal ? g_attn : attn_in;
    const int z  = blockIdx.y;             // b*H + h
    const int qt = blockIdx.x;             // q tile (0..15)
    const float* Ah = attn + (size_t)z * CS * CS;
    const float* Vh = g_V  + (size_t)z * CS * CDK;

    __shared__ __nv_bfloat16 Ahi[128 * PADK], Alo[128 * PADK];
    __shared__ __nv_bfloat16 Vhi[64 * PADK],  Vlo[64 * PADK];

    const int tid  = threadIdx.x;
    const int wid  = tid >> 5, lane = tid & 31;
    const int wm   = wid & 3,  wn   = wid >> 2;     // warp grid 4x2
    const int quad = lane >> 2, tq  = lane & 3;

    const int row0 = qt * 128;
    const int lrow = tid >> 1;            // attn row
    const int lk   = (tid & 1) * 16;      // k-half
    const int vk   = tid >> 3;            // 0..31 : V k-row
    const int vd   = (tid & 7) * 8;       // 0..56 : V dk base

    float acc[2][4][4];
    #pragma unroll
    for (int mi = 0; mi < 2; mi++)
        #pragma unroll
        for (int ni = 0; ni < 4; ni++)
            #pragma unroll
            for (int r = 0; r < 4; r++) acc[mi][ni][r] = 0.f;

    const int kend = (qt + 1) * 128;      // causal bound
    for (int kt = 0; kt < kend; kt += 32) {
        // prefetch
        float4 av[4];
        #pragma unroll
        for (int i = 0; i < 4; i++)
            av[i] = *(const float4*)(Ah + (size_t)(row0 + lrow) * CS + kt + lk + i * 4);
        float4 v0 = *(const float4*)(Vh + (size_t)(kt + vk) * CDK + vd);
        float4 v1 = *(const float4*)(Vh + (size_t)(kt + vk) * CDK + vd + 4);
        __syncthreads();

        #pragma unroll
        for (int i = 0; i < 4; i++) {
            uint2 hi, lo;
            split4(av[i], hi, lo);
            *(uint2*)(Ahi + lrow * PADK + lk + i * 4) = hi;
            *(uint2*)(Alo + lrow * PADK + lk + i * 4) = lo;
        }
        // V transposed store: Vs[dk][k]
        {
            const float vv[8] = {v0.x, v0.y, v0.z, v0.w, v1.x, v1.y, v1.z, v1.w};
            #pragma unroll
            for (int j = 0; j < 8; j++) {
                __nv_bfloat16 hi, lo;
                split1(vv[j], hi, lo);
                Vhi[(vd + j) * PADK + vk] = hi;
                Vlo[(vd + j) * PADK + vk] = lo;
            }
        }
        __syncthreads();

        #pragma unroll
        for (int k0 = 0; k0 < 32; k0 += 16) {
            uint32_t ah[2][4], al[2][4], bh[4][2], bl[4][2];
            #pragma unroll
            for (int mi = 0; mi < 2; mi++) {
                const int r0 = wm * 32 + mi * 16 + quad;
                const __nv_bfloat16* p = Ahi + r0 * PADK + k0 + tq * 2;
                const __nv_bfloat16* q = Alo + r0 * PADK + k0 + tq * 2;
                ah[mi][0] = *(const uint32_t*)p;
                ah[mi][1] = *(const uint32_t*)(p + 8 * PADK);
                ah[mi][2] = *(const uint32_t*)(p + 8);
                ah[mi][3] = *(const uint32_t*)(p + 8 * PADK + 8);
                al[mi][0] = *(const uint32_t*)q;
                al[mi][1] = *(const uint32_t*)(q + 8 * PADK);
                al[mi][2] = *(const uint32_t*)(q + 8);
                al[mi][3] = *(const uint32_t*)(q + 8 * PADK + 8);
            }
            #pragma unroll
            for (int ni = 0; ni < 4; ni++) {
                const int n0 = wn * 32 + ni * 8 + quad;
                const __nv_bfloat16* p = Vhi + n0 * PADK + k0 + tq * 2;
                const __nv_bfloat16* q = Vlo + n0 * PADK + k0 + tq * 2;
                bh[ni][0] = *(const uint32_t*)p;
                bh[ni][1] = *(const uint32_t*)(p + 8);
                bl[ni][0] = *(const uint32_t*)q;
                bl[ni][1] = *(const uint32_t*)(q + 8);
            }
            #pragma unroll
            for (int mi = 0; mi < 2; mi++)
                #pragma unroll
                for (int ni = 0; ni < 4; ni++) mma16816(acc[mi][ni], ah[mi], bh[ni]);
            #pragma unroll
            for (int mi = 0; mi < 2; mi++)
                #pragma unroll
                for (int ni = 0; ni < 4; ni++) mma16816(acc[mi][ni], al[mi], bh[ni]);
            #pragma unroll
            for (int mi = 0; mi < 2; mi++)
                #pragma unroll
                for (int ni = 0; ni < 4; ni++) mma16816(acc[mi][ni], ah[mi], bl[ni]);
        }
    }

    const int b = z >> 4, h = z & (CH - 1);
    #pragma unroll
    for (int mi = 0; mi < 2; mi++) {
        const int q0 = row0 + wm * 32 + mi * 16 + quad;
        #pragma unroll
        for (int ni = 0; ni < 4; ni++) {
            const int dk = wn * 32 + ni * 8 + tq * 2;
            *(float2*)&g_ctx[(((size_t)b * CS + q0) * CH + h) * CDK + dk] =
                make_float2(acc[mi][ni][0], acc[mi][ni][1]);
            *(float2*)&g_ctx[(((size_t)b * CS + q0 + 8) * CH + h) * CDK + dk] =
                make_float2(acc[mi][ni][2], acc[mi][ni][3]);
        }
    }
}

// ---------------------------------------------------------------------------
extern "C" void kernel_launch(void* const* d_in, const int* in_sizes, int n_in,
                              void* d_out, int out_size)
{
    const float* query = (const float*)d_in[0];
    const float* key   = (const float*)d_in[1];
    const float* value = (const float*)d_in[2];
    // d_in[3] = mask (causal by construction; unused)
    const float* w_q = (const float*)d_in[4];
    const float* w_k = (const float*)d_in[5];
    const float* w_v = (const float*)d_in[6];
    const float* w_o = (const float*)d_in[7];
    const float* b_o = (const float*)d_in[8];

    float* out = (float*)d_out;
    const int attn_in_out = ((size_t)out_size >= OUT_ELEMS + ATTN_ELEMS) ? 1 : 0;
    float* attn_ptr = attn_in_out ? (out + OUT_ELEMS) : nullptr;
    const int use_internal = attn_in_out ? 0 : 1;

    // 1. Q/K/V projections (mma.sync split-bf16)
    proj_mma<<<dim3(CD/128, CM/128, 3), 256>>>(query, key, value, w_q, w_k, w_v);

    // 2. causal scores (mma.sync split-bf16)
    scores_mma<<<dim3(CS/128, CS/128, CB*CH), 256>>>(attn_ptr, use_internal);

    // 3. softmax rows (vectorized; writes final attention_weights incl. zeros)
    softmax_kernel<<<CB*CH*CS, 256>>>(attn_ptr, use_internal);

    // 4. context = attn @ V (mma.sync split-bf16)
    context_mma<<<dim3(CS/128, CB*CH), 256>>>(attn_ptr, use_internal);

    // 5. output projection + bias (mma.sync split-bf16)
    outproj_mma<<<dim3(CD/128, CM/128), 256>>>(w_o, b_o, out);
}